// round 1
// baseline (speedup 1.0000x reference)
#include <cuda_runtime.h>
#include <math.h>

// Problem constants
#define LAYERS 4
#define S 2048
#define D 1024
#define HQ 16
#define KVH 4
#define HD 64
#define II 4096
#define VV 32000
#define EPSV 1e-6f

// ---------------- scratch (device globals; no allocations allowed) ----------
__device__ float g_h[S * D];            // residual stream
__device__ float g_x[S * D];            // normed activations
__device__ float g_q[S * HQ * HD];
__device__ float g_k[S * KVH * HD];
__device__ float g_v[S * KVH * HD];
__device__ float g_o[S * HQ * HD];
__device__ float g_gate[S * II];
__device__ float g_up[S * II];
__device__ float g_cos[S * 32];
__device__ float g_sin[S * 32];

// ---------------- RoPE table (double-precision trig: fast-math safe) --------
__global__ void rope_table_kernel() {
    int idx = blockIdx.x * blockDim.x + threadIdx.x;
    if (idx >= S * 32) return;
    int s = idx >> 5, i = idx & 31;
    double invf = exp(-((double)(2 * i) / (double)HD) * log(10000.0));
    float invf_f = (float)invf;                 // match ref's fp32 inv_freq
    float af = (float)s * invf_f;               // match ref's fp32 angle
    g_cos[idx] = (float)cos((double)af);        // exact cos of that fp32 angle
    g_sin[idx] = (float)sin((double)af);
}

// ---------------- embedding gather ------------------------------------------
__global__ void embed_kernel(const float* __restrict__ embed,
                             const int* __restrict__ ids) {
    int idx = blockIdx.x * blockDim.x + threadIdx.x;   // over S*D/4
    int s = idx / (D / 4);
    int c = idx % (D / 4);
    float4 v = ((const float4*)(embed + (size_t)ids[s] * D))[c];
    ((float4*)(g_h + (size_t)s * D))[c] = v;
}

// ---------------- RMSNorm ----------------------------------------------------
__global__ void rmsnorm_kernel(const float* __restrict__ X,
                               const float* __restrict__ w,
                               float* __restrict__ Y) {
    int row = blockIdx.x;
    const float* x = X + (size_t)row * D;
    float ss = 0.f;
    for (int i = threadIdx.x; i < D; i += blockDim.x) {
        float v = x[i];
        ss = fmaf(v, v, ss);
    }
    __shared__ float sred[32];
    #pragma unroll
    for (int off = 16; off; off >>= 1) ss += __shfl_xor_sync(0xffffffffu, ss, off);
    int wid = threadIdx.x >> 5, lid = threadIdx.x & 31;
    if (lid == 0) sred[wid] = ss;
    __syncthreads();
    if (wid == 0) {
        ss = (lid < (int)(blockDim.x >> 5)) ? sred[lid] : 0.f;
        #pragma unroll
        for (int off = 16; off; off >>= 1) ss += __shfl_xor_sync(0xffffffffu, ss, off);
        if (lid == 0) sred[0] = ss;
    }
    __syncthreads();
    float inv = rsqrtf(sred[0] / (float)D + EPSV);
    for (int i = threadIdx.x; i < D; i += blockDim.x)
        Y[(size_t)row * D + i] = w[i] * (x[i] * inv);
}

// ---------------- RoPE apply (in place) -------------------------------------
__global__ void rope_kernel(float* __restrict__ X, int nheads) {
    int idx = blockIdx.x * blockDim.x + threadIdx.x;   // over S*nheads*32
    int total = S * nheads * 32;
    if (idx >= total) return;
    int i = idx & 31;
    int h = (idx >> 5) % nheads;
    int s = idx / (32 * nheads);
    float c = g_cos[s * 32 + i], sn = g_sin[s * 32 + i];
    float* p = X + (size_t)s * nheads * HD + h * HD;
    float x1 = p[i], x2 = p[i + 32];
    p[i]      = x1 * c - x2 * sn;
    p[i + 32] = x2 * c + x1 * sn;
}

// ---------------- SiLU(gate) * up  (in place into g_gate) -------------------
__global__ void silu_mul_kernel() {
    int idx = blockIdx.x * blockDim.x + threadIdx.x;   // over S*II/4
    float4 g = ((const float4*)g_gate)[idx];
    float4 u = ((const float4*)g_up)[idx];
    g.x = g.x / (1.f + expf(-g.x)) * u.x;
    g.y = g.y / (1.f + expf(-g.y)) * u.y;
    g.z = g.z / (1.f + expf(-g.z)) * u.z;
    g.w = g.w / (1.f + expf(-g.w)) * u.w;
    ((float4*)g_gate)[idx] = g;
}

// ---------------- SGEMM: C[M,N] = A[M,K] @ B[K,N]  (row-major) --------------
// MODE 0: C = acc + bias (bias may be null)
// MODE 1: C += acc (residual accumulate)
#define BM 128
#define BN 128
#define BK 16
template <int MODE>
__global__ void __launch_bounds__(256)
sgemm_kernel(const float* __restrict__ A, const float* __restrict__ B,
             const float* __restrict__ bias, float* __restrict__ C,
             int M, int N, int K) {
    __shared__ float As[BK][BM];   // transposed A tile
    __shared__ float Bs[BK][BN];

    const int tid = threadIdx.x;
    const int row0 = blockIdx.y * BM;
    const int col0 = blockIdx.x * BN;

    // A-load mapping: rows tid/4 and tid/4+64, 4 k-floats at (tid&3)*4
    const int aRow = tid >> 2;
    const int aCol = (tid & 3) << 2;
    // B-load mapping: rows tid/32 and tid/32+8, 4 n-floats at (tid&31)*4
    const int bRow = tid >> 5;
    const int bCol = (tid & 31) << 2;

    const int ty = tid >> 4;   // 0..15 -> rows ty*8..+7
    const int tx = tid & 15;   // 0..15 -> cols tx*8..+7

    const float* Aptr = A + (size_t)row0 * K;
    const float* Bptr = B + col0;

    float acc[8][8];
    #pragma unroll
    for (int i = 0; i < 8; i++)
        #pragma unroll
        for (int j = 0; j < 8; j++) acc[i][j] = 0.f;

    for (int k0 = 0; k0 < K; k0 += BK) {
        float4 a0 = *(const float4*)(Aptr + (size_t)aRow * K + k0 + aCol);
        float4 a1 = *(const float4*)(Aptr + (size_t)(aRow + 64) * K + k0 + aCol);
        float4 b0 = *(const float4*)(Bptr + (size_t)(k0 + bRow) * N + bCol);
        float4 b1 = *(const float4*)(Bptr + (size_t)(k0 + bRow + 8) * N + bCol);
        __syncthreads();
        As[aCol + 0][aRow] = a0.x; As[aCol + 1][aRow] = a0.y;
        As[aCol + 2][aRow] = a0.z; As[aCol + 3][aRow] = a0.w;
        As[aCol + 0][aRow + 64] = a1.x; As[aCol + 1][aRow + 64] = a1.y;
        As[aCol + 2][aRow + 64] = a1.z; As[aCol + 3][aRow + 64] = a1.w;
        *(float4*)&Bs[bRow][bCol]     = b0;
        *(float4*)&Bs[bRow + 8][bCol] = b1;
        __syncthreads();

        #pragma unroll
        for (int kk = 0; kk < BK; kk++) {
            float ar[8], br[8];
            *(float4*)(ar)     = *(const float4*)&As[kk][ty * 8];
            *(float4*)(ar + 4) = *(const float4*)&As[kk][ty * 8 + 4];
            *(float4*)(br)     = *(const float4*)&Bs[kk][tx * 8];
            *(float4*)(br + 4) = *(const float4*)&Bs[kk][tx * 8 + 4];
            #pragma unroll
            for (int i = 0; i < 8; i++)
                #pragma unroll
                for (int j = 0; j < 8; j++)
                    acc[i][j] = fmaf(ar[i], br[j], acc[i][j]);
        }
    }

    float bb[8];
    if (MODE == 0) {
        #pragma unroll
        for (int j = 0; j < 8; j++)
            bb[j] = bias ? bias[col0 + tx * 8 + j] : 0.f;
    }

    #pragma unroll
    for (int i = 0; i < 8; i++) {
        size_t r = (size_t)(row0 + ty * 8 + i);
        float* cp = C + r * N + col0 + tx * 8;
        if (MODE == 0) {
            float4 v0 = make_float4(acc[i][0] + bb[0], acc[i][1] + bb[1],
                                    acc[i][2] + bb[2], acc[i][3] + bb[3]);
            float4 v1 = make_float4(acc[i][4] + bb[4], acc[i][5] + bb[5],
                                    acc[i][6] + bb[6], acc[i][7] + bb[7]);
            *(float4*)(cp)     = v0;
            *(float4*)(cp + 4) = v1;
        } else {
            float4 c0 = *(const float4*)(cp);
            float4 c1 = *(const float4*)(cp + 4);
            c0.x += acc[i][0]; c0.y += acc[i][1]; c0.z += acc[i][2]; c0.w += acc[i][3];
            c1.x += acc[i][4]; c1.y += acc[i][5]; c1.z += acc[i][6]; c1.w += acc[i][7];
            *(float4*)(cp)     = c0;
            *(float4*)(cp + 4) = c1;
        }
    }
}

// ---------------- Fused causal GQA attention (fp32 flash-style) -------------
// grid: (S/128, HQ), block: 128 threads; each thread owns one query row.
#define AKV 64
__global__ void __launch_bounds__(128)
attn_kernel() {
    __shared__ float Ks[AKV][HD];   // 16 KB
    __shared__ float Vs[AKV][HD];   // 16 KB

    const int hq = blockIdx.y;
    const int kvh = hq >> 2;                  // G = 4
    const int row = blockIdx.x * 128 + threadIdx.x;

    float qr[HD];
    #pragma unroll
    for (int d = 0; d < HD; d += 4) {
        float4 t = *(const float4*)&g_q[(size_t)row * (HQ * HD) + hq * HD + d];
        qr[d] = t.x; qr[d + 1] = t.y; qr[d + 2] = t.z; qr[d + 3] = t.w;
    }
    float o[HD];
    #pragma unroll
    for (int d = 0; d < HD; d++) o[d] = 0.f;
    float m = -INFINITY, l = 0.f;

    const int kend = (blockIdx.x + 1) * 128;   // exclusive key bound for tile
    for (int j0 = 0; j0 < kend; j0 += AKV) {
        __syncthreads();
        for (int t = threadIdx.x; t < AKV * (HD / 4); t += 128) {
            int r = t / (HD / 4);
            int c = (t % (HD / 4)) * 4;
            size_t g = (size_t)(j0 + r) * (KVH * HD) + kvh * HD + c;
            *(float4*)&Ks[r][c] = *(const float4*)&g_k[g];
            *(float4*)&Vs[r][c] = *(const float4*)&g_v[g];
        }
        __syncthreads();

        int jmax = row + 1 - j0;
        if (jmax > AKV) jmax = AKV;
        for (int j = 0; j < jmax; j++) {
            float s0 = 0.f, s1 = 0.f, s2 = 0.f, s3 = 0.f;
            #pragma unroll
            for (int d = 0; d < HD; d += 4) {
                float4 kk4 = *(const float4*)&Ks[j][d];
                s0 = fmaf(qr[d],     kk4.x, s0);
                s1 = fmaf(qr[d + 1], kk4.y, s1);
                s2 = fmaf(qr[d + 2], kk4.z, s2);
                s3 = fmaf(qr[d + 3], kk4.w, s3);
            }
            float s = ((s0 + s1) + (s2 + s3)) * 0.125f;
            if (s > m) {                       // lazy rescale (rare)
                float corr = expf(m - s);      // exp(-inf)=0 on first key
                l *= corr;
                #pragma unroll
                for (int d = 0; d < HD; d++) o[d] *= corr;
                m = s;
            }
            float p = expf(s - m);
            l += p;
            #pragma unroll
            for (int d = 0; d < HD; d += 4) {
                float4 vv = *(const float4*)&Vs[j][d];
                o[d]     = fmaf(p, vv.x, o[d]);
                o[d + 1] = fmaf(p, vv.y, o[d + 1]);
                o[d + 2] = fmaf(p, vv.z, o[d + 2]);
                o[d + 3] = fmaf(p, vv.w, o[d + 3]);
            }
        }
    }

    float inv = 1.f / l;
    #pragma unroll
    for (int d = 0; d < HD; d += 4) {
        float4 t = make_float4(o[d] * inv, o[d + 1] * inv, o[d + 2] * inv, o[d + 3] * inv);
        *(float4*)&g_o[(size_t)row * (HQ * HD) + hq * HD + d] = t;
    }
}

// ---------------- host-side helpers ------------------------------------------
static void launch_gemm(const float* A, const float* B, const float* bias,
                        float* C, int M, int N, int K, int mode) {
    dim3 grid(N / BN, M / BM);
    if (mode == 0) sgemm_kernel<0><<<grid, 256>>>(A, B, bias, C, M, N, K);
    else           sgemm_kernel<1><<<grid, 256>>>(A, B, bias, C, M, N, K);
}

extern "C" void kernel_launch(void* const* d_in, const int* in_sizes, int n_in,
                              void* d_out, int out_size) {
    const float* embed  = (const float*)d_in[0];
    const float* ln1    = (const float*)d_in[1];
    const float* qw     = (const float*)d_in[2];
    const float* qb     = (const float*)d_in[3];
    const float* kw     = (const float*)d_in[4];
    const float* kb     = (const float*)d_in[5];
    const float* vw     = (const float*)d_in[6];
    const float* vb     = (const float*)d_in[7];
    const float* ow     = (const float*)d_in[8];
    const float* ln2    = (const float*)d_in[9];
    const float* gw     = (const float*)d_in[10];
    const float* uw     = (const float*)d_in[11];
    const float* dw     = (const float*)d_in[12];
    const float* norm_w = (const float*)d_in[13];
    const float* lm_w   = (const float*)d_in[14];
    const int*   ids    = (const int*)d_in[15];
    float* out = (float*)d_out;

    float *p_h, *p_x, *p_q, *p_k, *p_v, *p_o, *p_gate, *p_up;
    cudaGetSymbolAddress((void**)&p_h, g_h);
    cudaGetSymbolAddress((void**)&p_x, g_x);
    cudaGetSymbolAddress((void**)&p_q, g_q);
    cudaGetSymbolAddress((void**)&p_k, g_k);
    cudaGetSymbolAddress((void**)&p_v, g_v);
    cudaGetSymbolAddress((void**)&p_o, g_o);
    cudaGetSymbolAddress((void**)&p_gate, g_gate);
    cudaGetSymbolAddress((void**)&p_up, g_up);

    rope_table_kernel<<<(S * 32 + 255) / 256, 256>>>();
    embed_kernel<<<(S * D / 4) / 256, 256>>>(embed, ids);

    for (int l = 0; l < LAYERS; l++) {
        rmsnorm_kernel<<<S, 256>>>(p_h, ln1 + (size_t)l * D, p_x);
        launch_gemm(p_x, qw + (size_t)l * D * HQ * HD, qb + (size_t)l * HQ * HD,
                    p_q, S, HQ * HD, D, 0);
        launch_gemm(p_x, kw + (size_t)l * D * KVH * HD, kb + (size_t)l * KVH * HD,
                    p_k, S, KVH * HD, D, 0);
        launch_gemm(p_x, vw + (size_t)l * D * KVH * HD, vb + (size_t)l * KVH * HD,
                    p_v, S, KVH * HD, D, 0);
        rope_kernel<<<(S * HQ * 32) / 256, 256>>>(p_q, HQ);
        rope_kernel<<<(S * KVH * 32) / 256, 256>>>(p_k, KVH);
        attn_kernel<<<dim3(S / 128, HQ), 128>>>();
        launch_gemm(p_o, ow + (size_t)l * HQ * HD * D, nullptr, p_h, S, D, HQ * HD, 1);
        rmsnorm_kernel<<<S, 256>>>(p_h, ln2 + (size_t)l * D, p_x);
        launch_gemm(p_x, gw + (size_t)l * D * II, nullptr, p_gate, S, II, D, 0);
        launch_gemm(p_x, uw + (size_t)l * D * II, nullptr, p_up, S, II, D, 0);
        silu_mul_kernel<<<(S * II / 4) / 256, 256>>>();
        launch_gemm(p_gate, dw + (size_t)l * II * D, nullptr, p_h, S, D, II, 1);
    }

    rmsnorm_kernel<<<S, 256>>>(p_h, norm_w, p_x);
    launch_gemm(p_x, lm_w, nullptr, out, S, VV, D, 0);
}

// round 3
// speedup vs baseline: 1.2188x; 1.2188x over previous
#include <cuda_runtime.h>
#include <math.h>
#include <stdint.h>

// Problem constants
#define LAYERS 4
#define S 2048
#define D 1024
#define HQ 16
#define KVH 4
#define HD 64
#define II 4096
#define VV 32000
#define EPSV 1e-6f

// ---------------- scratch (device globals; no allocations allowed) ----------
__device__ float g_h[S * D];            // residual stream
__device__ float g_x[S * D];            // normed activations
__device__ float g_q[S * HQ * HD];
__device__ float g_k[S * KVH * HD];
__device__ float g_v[S * KVH * HD];
__device__ float g_o[S * HQ * HD];
__device__ float g_gate[S * II];
__device__ float g_up[S * II];
__device__ float g_cos[S * 32];
__device__ float g_sin[S * 32];

// ---------------- RoPE table (double-precision trig: fast-math safe) --------
__global__ void rope_table_kernel() {
    int idx = blockIdx.x * blockDim.x + threadIdx.x;
    if (idx >= S * 32) return;
    int s = idx >> 5, i = idx & 31;
    double invf = exp(-((double)(2 * i) / (double)HD) * log(10000.0));
    float invf_f = (float)invf;                 // match ref's fp32 inv_freq
    float af = (float)s * invf_f;               // match ref's fp32 angle
    g_cos[idx] = (float)cos((double)af);        // exact cos of that fp32 angle
    g_sin[idx] = (float)sin((double)af);
}

// ---------------- embedding gather ------------------------------------------
__global__ void embed_kernel(const float* __restrict__ embed,
                             const int* __restrict__ ids) {
    int idx = blockIdx.x * blockDim.x + threadIdx.x;   // over S*D/4
    int s = idx / (D / 4);
    int c = idx % (D / 4);
    float4 v = ((const float4*)(embed + (size_t)ids[s] * D))[c];
    ((float4*)(g_h + (size_t)s * D))[c] = v;
}

// ---------------- RMSNorm ----------------------------------------------------
__global__ void rmsnorm_kernel(const float* __restrict__ X,
                               const float* __restrict__ w,
                               float* __restrict__ Y) {
    int row = blockIdx.x;
    const float* x = X + (size_t)row * D;
    float ss = 0.f;
    for (int i = threadIdx.x; i < D; i += blockDim.x) {
        float v = x[i];
        ss = fmaf(v, v, ss);
    }
    __shared__ float sred[32];
    #pragma unroll
    for (int off = 16; off; off >>= 1) ss += __shfl_xor_sync(0xffffffffu, ss, off);
    int wid = threadIdx.x >> 5, lid = threadIdx.x & 31;
    if (lid == 0) sred[wid] = ss;
    __syncthreads();
    if (wid == 0) {
        ss = (lid < (int)(blockDim.x >> 5)) ? sred[lid] : 0.f;
        #pragma unroll
        for (int off = 16; off; off >>= 1) ss += __shfl_xor_sync(0xffffffffu, ss, off);
        if (lid == 0) sred[0] = ss;
    }
    __syncthreads();
    float inv = rsqrtf(sred[0] / (float)D + EPSV);
    for (int i = threadIdx.x; i < D; i += blockDim.x)
        Y[(size_t)row * D + i] = w[i] * (x[i] * inv);
}

// ---------------- RoPE apply (in place) -------------------------------------
__global__ void rope_kernel(float* __restrict__ X, int nheads) {
    int idx = blockIdx.x * blockDim.x + threadIdx.x;   // over S*nheads*32
    int total = S * nheads * 32;
    if (idx >= total) return;
    int i = idx & 31;
    int h = (idx >> 5) % nheads;
    int s = idx / (32 * nheads);
    float c = g_cos[s * 32 + i], sn = g_sin[s * 32 + i];
    float* p = X + (size_t)s * nheads * HD + h * HD;
    float x1 = p[i], x2 = p[i + 32];
    p[i]      = x1 * c - x2 * sn;
    p[i + 32] = x2 * c + x1 * sn;
}

// ---------------- SiLU(gate) * up  (in place into g_gate) -------------------
__global__ void silu_mul_kernel() {
    int idx = blockIdx.x * blockDim.x + threadIdx.x;   // over S*II/4
    float4 g = ((const float4*)g_gate)[idx];
    float4 u = ((const float4*)g_up)[idx];
    g.x = g.x / (1.f + expf(-g.x)) * u.x;
    g.y = g.y / (1.f + expf(-g.y)) * u.y;
    g.z = g.z / (1.f + expf(-g.z)) * u.z;
    g.w = g.w / (1.f + expf(-g.w)) * u.w;
    ((float4*)g_gate)[idx] = g;
}

// ==================== 3xTF32 tensor-core GEMM ================================
// C[M,N] = A[M,K] @ B[K,N], row-major. mode 0: C = acc + bias; mode 1: C += acc
// Each fp32 operand split hi/lo in tf32; product = hi*hi + lo*hi + hi*lo.
// Block tile 128 x (64*NWN), warp tile 64x64, BK=16.
// smem holds operands in mma-fragment-native layout (conflict-free LDS.128/64).

struct GemmSeg {
    const float* B;
    const float* bias;
    float* C;
    int N;
    int nx;   // number of block-columns for this segment
};

__device__ __forceinline__ uint32_t f2tf32(float f) {
    uint32_t u;
    asm("cvt.rna.tf32.f32 %0, %1;" : "=r"(u) : "f"(f));
    return u;
}

#define MMA_TF32(c, a, b)                                                     \
    asm volatile(                                                             \
        "mma.sync.aligned.m16n8k8.row.col.f32.tf32.tf32.f32 "                 \
        "{%0,%1,%2,%3},{%4,%5,%6,%7},{%8,%9},{%0,%1,%2,%3};"                  \
        : "+f"(c[0]), "+f"(c[1]), "+f"(c[2]), "+f"(c[3])                      \
        : "r"(a.x), "r"(a.y), "r"(a.z), "r"(a.w), "r"(b.x), "r"(b.y))

// A frag-layout offset (tile-local m in [0,128), k in [0,16))
__device__ __forceinline__ int offA(int m, int k) {
    int lane = ((m & 7) << 2) + (k & 3);
    int reg = ((m >> 3) & 1) + 2 * ((k >> 2) & 1);
    return ((k >> 3) * 8 + (m >> 4)) * 132 + lane * 4 + reg;
}
// B frag-layout offset (k in [0,16), tile-local n in [0,BN))
template <int NWN>
__device__ __forceinline__ int offB(int k, int n) {
    int lane = ((n & 7) << 2) + (k & 3);
    int reg = (k >> 2) & 1;
    return ((k >> 3) * (8 * NWN) + (n >> 3)) * 66 + lane * 2 + reg;
}

template <int NWN>   // NWN=2 -> BN=128, 128 thr; NWN=4 -> BN=256, 256 thr
__global__ void __launch_bounds__(64 * NWN, 1)
mm_kernel(const float* __restrict__ A, GemmSeg s0, GemmSeg s1, GemmSeg s2,
          int K, int mode) {
    constexpr int T = 64 * NWN;       // threads
    constexpr int BN = 64 * NWN;
    constexpr int BK = 16;
    constexpr int ASZ = 2112;         // floats per A buffer per precision (16 blk * 132)
    constexpr int BSZ = 1056 * NWN;   // floats per B buffer per precision
    constexpr int A_LD = 512 / T;     // float4 per thread for A tile (128x16)
    constexpr int B_LD = 4;           // float4 per thread for B tile (16xBN)

    extern __shared__ float sm[];
    // layout: [buf(2)][prec(2)] for A then B
    uint32_t* smA = (uint32_t*)sm;                  // 2*2*ASZ
    uint32_t* smB = (uint32_t*)(sm + 4 * ASZ);      // 2*2*BSZ

    // segment select
    int bx = blockIdx.x;
    const float* Bp;
    const float* bias;
    float* Cp;
    int N;
    if (bx < s0.nx) {
        Bp = s0.B; bias = s0.bias; Cp = s0.C; N = s0.N;
    } else if (bx < s0.nx + s1.nx) {
        bx -= s0.nx;
        Bp = s1.B; bias = s1.bias; Cp = s1.C; N = s1.N;
    } else {
        bx -= s0.nx + s1.nx;
        Bp = s2.B; bias = s2.bias; Cp = s2.C; N = s2.N;
    }
    const int row0 = blockIdx.y * 128;
    const int col0 = bx * BN;

    const int tid = threadIdx.x;
    const int lane = tid & 31;
    const int warp = tid >> 5;
    const int wm = warp & 1;        // 0..1  -> 64 rows
    const int wn = warp >> 1;       // 0..NWN-1 -> 64 cols

    float acc[4][8][4];
    #pragma unroll
    for (int i = 0; i < 4; i++)
        #pragma unroll
        for (int j = 0; j < 8; j++)
            #pragma unroll
            for (int r = 0; r < 4; r++) acc[i][j][r] = 0.f;

    float4 av[A_LD], bv[B_LD];

    auto ldg_tile = [&](int k0) {
        #pragma unroll
        for (int i = 0; i < A_LD; i++) {
            int idx = tid + i * T;                // over 512 float4 (128x16)
            int r = idx >> 2, c4 = (idx & 3) << 2;
            av[i] = *(const float4*)(A + (size_t)(row0 + r) * K + k0 + c4);
        }
        #pragma unroll
        for (int i = 0; i < B_LD; i++) {
            int idx = tid + i * T;                // over 4*BN float4 (16xBN)
            int kk = idx / (BN / 4);
            int n4 = (idx % (BN / 4)) << 2;
            bv[i] = *(const float4*)(Bp + (size_t)(k0 + kk) * N + col0 + n4);
        }
    };
    auto split_store = [](uint32_t* hi, uint32_t* lo, int ofs, float f) {
        uint32_t h = f2tf32(f);
        hi[ofs] = h;
        lo[ofs] = f2tf32(f - __uint_as_float(h));
    };
    auto sts_tile = [&](int buf) {
        uint32_t* a_hi = smA + buf * 2 * ASZ;
        uint32_t* a_lo = a_hi + ASZ;
        uint32_t* b_hi = smB + buf * 2 * BSZ;
        uint32_t* b_lo = b_hi + BSZ;
        #pragma unroll
        for (int i = 0; i < A_LD; i++) {
            int idx = tid + i * T;
            int r = idx >> 2, c4 = (idx & 3) << 2;
            split_store(a_hi, a_lo, offA(r, c4 + 0), av[i].x);
            split_store(a_hi, a_lo, offA(r, c4 + 1), av[i].y);
            split_store(a_hi, a_lo, offA(r, c4 + 2), av[i].z);
            split_store(a_hi, a_lo, offA(r, c4 + 3), av[i].w);
        }
        #pragma unroll
        for (int i = 0; i < B_LD; i++) {
            int idx = tid + i * T;
            int kk = idx / (BN / 4);
            int n4 = (idx % (BN / 4)) << 2;
            split_store(b_hi, b_lo, offB<NWN>(kk, n4 + 0), bv[i].x);
            split_store(b_hi, b_lo, offB<NWN>(kk, n4 + 1), bv[i].y);
            split_store(b_hi, b_lo, offB<NWN>(kk, n4 + 2), bv[i].z);
            split_store(b_hi, b_lo, offB<NWN>(kk, n4 + 3), bv[i].w);
        }
    };

    const int ntiles = K / BK;
    ldg_tile(0);
    sts_tile(0);
    __syncthreads();

    int cur = 0;
    for (int it = 0; it < ntiles; it++) {
        bool has_next = (it + 1 < ntiles);
        if (has_next) ldg_tile((it + 1) * BK);

        const uint32_t* Ahi = smA + cur * 2 * ASZ;
        const uint32_t* Alo = Ahi + ASZ;
        const uint32_t* Bhi = smB + cur * 2 * BSZ;
        const uint32_t* Blo = Bhi + BSZ;
        #pragma unroll
        for (int ks = 0; ks < 2; ks++) {
            uint4 afh[4];
            uint2 bfh[8];
            #pragma unroll
            for (int mf = 0; mf < 4; mf++)
                afh[mf] = *(const uint4*)&Ahi[(ks * 8 + wm * 4 + mf) * 132 + lane * 4];
            #pragma unroll
            for (int nf = 0; nf < 8; nf++)
                bfh[nf] = *(const uint2*)&Bhi[(ks * 8 * NWN + wn * 8 + nf) * 66 + lane * 2];
            // pass 1: hi * hi
            #pragma unroll
            for (int mf = 0; mf < 4; mf++)
                #pragma unroll
                for (int nf = 0; nf < 8; nf++)
                    MMA_TF32(acc[mf][nf], afh[mf], bfh[nf]);
            // pass 2: lo * hi
            {
                uint4 afl[4];
                #pragma unroll
                for (int mf = 0; mf < 4; mf++)
                    afl[mf] = *(const uint4*)&Alo[(ks * 8 + wm * 4 + mf) * 132 + lane * 4];
                #pragma unroll
                for (int mf = 0; mf < 4; mf++)
                    #pragma unroll
                    for (int nf = 0; nf < 8; nf++)
                        MMA_TF32(acc[mf][nf], afl[mf], bfh[nf]);
            }
            // pass 3: hi * lo
            {
                uint2 bfl[8];
                #pragma unroll
                for (int nf = 0; nf < 8; nf++)
                    bfl[nf] = *(const uint2*)&Blo[(ks * 8 * NWN + wn * 8 + nf) * 66 + lane * 2];
                #pragma unroll
                for (int mf = 0; mf < 4; mf++)
                    #pragma unroll
                    for (int nf = 0; nf < 8; nf++)
                        MMA_TF32(acc[mf][nf], afh[mf], bfl[nf]);
            }
        }

        if (has_next) sts_tile(cur ^ 1);
        __syncthreads();
        cur ^= 1;
    }

    // epilogue
    const int g = lane >> 2, tg = lane & 3;
    #pragma unroll
    for (int nf = 0; nf < 8; nf++) {
        int cc = col0 + wn * 64 + nf * 8 + tg * 2;
        float b0 = 0.f, b1 = 0.f;
        if (mode == 0 && bias) { b0 = bias[cc]; b1 = bias[cc + 1]; }
        #pragma unroll
        for (int mf = 0; mf < 4; mf++) {
            int rr = row0 + wm * 64 + mf * 16 + g;
            float2* p0 = (float2*)&Cp[(size_t)rr * N + cc];
            float2* p1 = (float2*)&Cp[(size_t)(rr + 8) * N + cc];
            if (mode == 0) {
                float2 v0 = make_float2(acc[mf][nf][0] + b0, acc[mf][nf][1] + b1);
                float2 v1 = make_float2(acc[mf][nf][2] + b0, acc[mf][nf][3] + b1);
                *p0 = v0; *p1 = v1;
            } else {
                float2 o0 = *p0, o1 = *p1;
                o0.x += acc[mf][nf][0]; o0.y += acc[mf][nf][1];
                o1.x += acc[mf][nf][2]; o1.y += acc[mf][nf][3];
                *p0 = o0; *p1 = o1;
            }
        }
    }
}

// ---------------- Fused causal GQA attention (fp32 flash-style) -------------
#define AKV 64
__global__ void __launch_bounds__(128)
attn_kernel() {
    __shared__ float Ks[AKV][HD];
    __shared__ float Vs[AKV][HD];

    const int hq = blockIdx.y;
    const int kvh = hq >> 2;                  // G = 4
    const int row = blockIdx.x * 128 + threadIdx.x;

    float qr[HD];
    #pragma unroll
    for (int d = 0; d < HD; d += 4) {
        float4 t = *(const float4*)&g_q[(size_t)row * (HQ * HD) + hq * HD + d];
        qr[d] = t.x; qr[d + 1] = t.y; qr[d + 2] = t.z; qr[d + 3] = t.w;
    }
    float o[HD];
    #pragma unroll
    for (int d = 0; d < HD; d++) o[d] = 0.f;
    float m = -INFINITY, l = 0.f;

    const int kend = (blockIdx.x + 1) * 128;
    for (int j0 = 0; j0 < kend; j0 += AKV) {
        __syncthreads();
        for (int t = threadIdx.x; t < AKV * (HD / 4); t += 128) {
            int r = t / (HD / 4);
            int c = (t % (HD / 4)) * 4;
            size_t gofs = (size_t)(j0 + r) * (KVH * HD) + kvh * HD + c;
            *(float4*)&Ks[r][c] = *(const float4*)&g_k[gofs];
            *(float4*)&Vs[r][c] = *(const float4*)&g_v[gofs];
        }
        __syncthreads();

        int jmax = row + 1 - j0;
        if (jmax > AKV) jmax = AKV;
        for (int j = 0; j < jmax; j++) {
            float s0 = 0.f, s1 = 0.f, s2 = 0.f, s3 = 0.f;
            #pragma unroll
            for (int d = 0; d < HD; d += 4) {
                float4 kk4 = *(const float4*)&Ks[j][d];
                s0 = fmaf(qr[d],     kk4.x, s0);
                s1 = fmaf(qr[d + 1], kk4.y, s1);
                s2 = fmaf(qr[d + 2], kk4.z, s2);
                s3 = fmaf(qr[d + 3], kk4.w, s3);
            }
            float s = ((s0 + s1) + (s2 + s3)) * 0.125f;
            if (s > m) {
                float corr = expf(m - s);
                l *= corr;
                #pragma unroll
                for (int d = 0; d < HD; d++) o[d] *= corr;
                m = s;
            }
            float p = expf(s - m);
            l += p;
            #pragma unroll
            for (int d = 0; d < HD; d += 4) {
                float4 vv = *(const float4*)&Vs[j][d];
                o[d]     = fmaf(p, vv.x, o[d]);
                o[d + 1] = fmaf(p, vv.y, o[d + 1]);
                o[d + 2] = fmaf(p, vv.z, o[d + 2]);
                o[d + 3] = fmaf(p, vv.w, o[d + 3]);
            }
        }
    }

    float inv = 1.f / l;
    #pragma unroll
    for (int d = 0; d < HD; d += 4) {
        float4 t = make_float4(o[d] * inv, o[d + 1] * inv, o[d + 2] * inv, o[d + 3] * inv);
        *(float4*)&g_o[(size_t)row * (HQ * HD) + hq * HD + d] = t;
    }
}

// ---------------- host side ---------------------------------------------------
static const int SMEM2 = (4 * 2112 + 4 * 1056 * 2) * 4;   // 67584 B
static const int SMEM4 = (4 * 2112 + 4 * 1056 * 4) * 4;   // 101376 B

static GemmSeg mkseg(const float* B, const float* bias, float* C, int N, int nx) {
    GemmSeg s; s.B = B; s.bias = bias; s.C = C; s.N = N; s.nx = nx; return s;
}

extern "C" void kernel_launch(void* const* d_in, const int* in_sizes, int n_in,
                              void* d_out, int out_size) {
    const float* embed  = (const float*)d_in[0];
    const float* ln1    = (const float*)d_in[1];
    const float* qw     = (const float*)d_in[2];
    const float* qb     = (const float*)d_in[3];
    const float* kw     = (const float*)d_in[4];
    const float* kb     = (const float*)d_in[5];
    const float* vw     = (const float*)d_in[6];
    const float* vb     = (const float*)d_in[7];
    const float* ow     = (const float*)d_in[8];
    const float* ln2    = (const float*)d_in[9];
    const float* gw     = (const float*)d_in[10];
    const float* uw     = (const float*)d_in[11];
    const float* dw     = (const float*)d_in[12];
    const float* norm_w = (const float*)d_in[13];
    const float* lm_w   = (const float*)d_in[14];
    const int*   ids    = (const int*)d_in[15];
    float* out = (float*)d_out;

    float *p_h, *p_x, *p_q, *p_k, *p_v, *p_o, *p_gate, *p_up;
    cudaGetSymbolAddress((void**)&p_h, g_h);
    cudaGetSymbolAddress((void**)&p_x, g_x);
    cudaGetSymbolAddress((void**)&p_q, g_q);
    cudaGetSymbolAddress((void**)&p_k, g_k);
    cudaGetSymbolAddress((void**)&p_v, g_v);
    cudaGetSymbolAddress((void**)&p_o, g_o);
    cudaGetSymbolAddress((void**)&p_gate, g_gate);
    cudaGetSymbolAddress((void**)&p_up, g_up);

    static bool attr_done = false;
    if (!attr_done) {
        cudaFuncSetAttribute(mm_kernel<2>, cudaFuncAttributeMaxDynamicSharedMemorySize, SMEM2);
        cudaFuncSetAttribute(mm_kernel<4>, cudaFuncAttributeMaxDynamicSharedMemorySize, SMEM4);
        attr_done = true;
    }

    GemmSeg z = mkseg(nullptr, nullptr, nullptr, 0, 0);

    rope_table_kernel<<<(S * 32 + 255) / 256, 256>>>();
    embed_kernel<<<(S * D / 4) / 256, 256>>>(embed, ids);

    for (int l = 0; l < LAYERS; l++) {
        rmsnorm_kernel<<<S, 256>>>(p_h, ln1 + (size_t)l * D, p_x);

        // fused QKV projection (3xtf32 tensor cores), grid 12x16
        {
            GemmSeg sq = mkseg(qw + (size_t)l * D * HQ * HD, qb + (size_t)l * HQ * HD, p_q, HQ * HD, 8);
            GemmSeg sk = mkseg(kw + (size_t)l * D * KVH * HD, kb + (size_t)l * KVH * HD, p_k, KVH * HD, 2);
            GemmSeg sv = mkseg(vw + (size_t)l * D * KVH * HD, vb + (size_t)l * KVH * HD, p_v, KVH * HD, 2);
            mm_kernel<2><<<dim3(12, 16), 128, SMEM2>>>(p_x, sq, sk, sv, D, 0);
        }
        rope_kernel<<<(S * HQ * 32) / 256, 256>>>(p_q, HQ);
        rope_kernel<<<(S * KVH * 32) / 256, 256>>>(p_k, KVH);
        attn_kernel<<<dim3(S / 128, HQ), 128>>>();

        // O projection: h += o @ ow
        {
            GemmSeg so = mkseg(ow + (size_t)l * HQ * HD * D, nullptr, p_h, D, 8);
            mm_kernel<2><<<dim3(8, 16), 128, SMEM2>>>(p_o, so, z, z, HQ * HD, 1);
        }
        rmsnorm_kernel<<<S, 256>>>(p_h, ln2 + (size_t)l * D, p_x);

        // fused gate+up, grid 32x16
        {
            GemmSeg sg = mkseg(gw + (size_t)l * D * II, nullptr, p_gate, II, 16);
            GemmSeg su = mkseg(uw + (size_t)l * D * II, nullptr, p_up, II, 16);
            mm_kernel<4><<<dim3(32, 16), 256, SMEM4>>>(p_x, sg, su, z, D, 0);
        }
        silu_mul_kernel<<<(S * II / 4) / 256, 256>>>();

        // down projection: h += act @ dw
        {
            GemmSeg sd = mkseg(dw + (size_t)l * II * D, nullptr, p_h, D, 8);
            mm_kernel<2><<<dim3(8, 16), 128, SMEM2>>>(p_gate, sd, z, z, II, 1);
        }
    }

    rmsnorm_kernel<<<S, 256>>>(p_h, norm_w, p_x);
    {
        GemmSeg sl = mkseg(lm_w, nullptr, out, VV, 125);
        mm_kernel<4><<<dim3(125, 16), 256, SMEM4>>>(p_x, sl, z, z, D, 0);
    }
}